// round 11
// baseline (speedup 1.0000x reference)
#include <cuda_runtime.h>
#include <cuda_fp16.h>
#include <cstdint>

#define N_GENES 16384
#define N_REG   8192
#define D_MODEL 256
#define OUT_DIM 128
#define ALPHA   0.2f

#define TI 64                    // regulon rows per i-tile
#define TJ 64                    // j per tile (MMA K)
#define NTJ 256                  // j-tiles per i-tile
#define N_ITILES (N_REG / TI)    // 128
#define NJOBS (N_ITILES * NTJ)   // 32768
#define GRID_ATTN 304            // 152 SMs x 2 CTAs
#define THREADS 512

// smem layout (per CTA 80 KB -> 2 CTAs/SM)
#define SM_P    0                      // 2 x 8 KB P double buffer
#define SM_V    16384                  // 4 x 16 KB V stages (fp16, 2 swizzled 64-col atoms)
#define SMEM_BYTES 81920

// ---------------- device scratch ----------------
__device__ __align__(16) __half g_whh[N_GENES * OUT_DIM];   // w_h fp16, row-major
__device__ float  g_wh1[N_REG];
__device__ float  g_wh2[N_GENES];
__device__ float  g_F1 [N_GENES];
__device__ float  g_F2 [N_GENES];
__device__ float  g_G1 [N_REG];
__device__ float  g_G2 [N_REG];
__device__ unsigned g_w2max_bits;
__device__ float  g_D  [(size_t)N_REG * OUT_DIM];           // accumulated D (atomics)
__device__ float  g_S  [N_REG];                             // accumulated S (atomics)

// ---------------- helpers ----------------
static __device__ __forceinline__ uint32_t swz(uint32_t x) { return x ^ ((x >> 3) & 0x70); }
static __device__ __forceinline__ uint32_t smem_u32(const void* p) {
    return (uint32_t)__cvta_generic_to_shared(p);
}
static __device__ __forceinline__ uint64_t pk2(float x, float y) {
    uint64_t r; asm("mov.b64 %0, {%1, %2};" : "=l"(r) : "f"(x), "f"(y)); return r;
}
static __device__ __forceinline__ void fma2(uint64_t& acc, uint64_t a, uint64_t b) {
    asm volatile("fma.rn.f32x2 %0, %1, %2, %0;" : "+l"(acc) : "l"(a), "l"(b));
}
static __device__ __forceinline__ unsigned fenc(float f) {
    unsigned u = __float_as_uint(f);
    return (u & 0x80000000u) ? ~u : (u | 0x80000000u);
}
static __device__ __forceinline__ float fdec(unsigned k) {
    unsigned u = (k & 0x80000000u) ? (k ^ 0x80000000u) : ~k;
    return __uint_as_float(u);
}

// ---------------- K1: w_h = input @ W  (+fused wh1/wh2/max) ----------------
__global__ void k_gemm1(const float* __restrict__ inp, const float* __restrict__ W,
                        const float* __restrict__ a) {
    __shared__ __align__(16) float s_t[D_MODEL][8];   // [k][r]
    __shared__ float sred[4][16];
    const int c  = threadIdx.x;          // 0..127
    const int r0 = blockIdx.x * 8;
    if (blockIdx.x == 0 && c == 0) g_w2max_bits = 0u;
    #pragma unroll
    for (int u = 0; u < 16; u++) {
        const int idx = c + u * 128;
        const int r = idx >> 8, k = idx & 255;
        s_t[k][r] = inp[(size_t)(r0 + r) * D_MODEL + k];
    }
    __syncthreads();

    uint64_t a01 = 0, a23 = 0, a45 = 0, a67 = 0;
    #pragma unroll 4
    for (int k = 0; k < D_MODEL; k++) {
        const float w = __ldg(&W[k * OUT_DIM + c]);
        const uint64_t ww = pk2(w, w);
        ulonglong2 lo = *(const ulonglong2*)&s_t[k][0];
        ulonglong2 hi = *(const ulonglong2*)&s_t[k][4];
        fma2(a01, lo.x, ww);
        fma2(a23, lo.y, ww);
        fma2(a45, hi.x, ww);
        fma2(a67, hi.y, ww);
    }
    float v[8];
    v[0] = __uint_as_float((uint32_t)a01); v[1] = __uint_as_float((uint32_t)(a01 >> 32));
    v[2] = __uint_as_float((uint32_t)a23); v[3] = __uint_as_float((uint32_t)(a23 >> 32));
    v[4] = __uint_as_float((uint32_t)a45); v[5] = __uint_as_float((uint32_t)(a45 >> 32));
    v[6] = __uint_as_float((uint32_t)a67); v[7] = __uint_as_float((uint32_t)(a67 >> 32));
    #pragma unroll
    for (int r = 0; r < 8; r++)
        g_whh[(size_t)(r0 + r) * OUT_DIM + c] = __float2half(v[r]);

    const float a1 = a[c], a2 = a[OUT_DIM + c];
    const int warp = c >> 5, lane = c & 31;
    #pragma unroll
    for (int r = 0; r < 8; r++) {
        float u1 = v[r] * a1, u2 = v[r] * a2;
        #pragma unroll
        for (int o = 16; o; o >>= 1) {
            u1 += __shfl_xor_sync(0xffffffffu, u1, o);
            u2 += __shfl_xor_sync(0xffffffffu, u2, o);
        }
        if (lane == 0) { sred[warp][r] = u1; sred[warp][8 + r] = u2; }
    }
    __syncthreads();
    if (c < 32) {
        float val = (c < 16) ? (sred[0][c] + sred[1][c] + sred[2][c] + sred[3][c]) : -1e30f;
        if (c < 8) { if (r0 + c < N_REG) g_wh1[r0 + c] = val; }
        else if (c < 16) g_wh2[r0 + c - 8] = val;
        float m = (c >= 8 && c < 16) ? val : -1e30f;
        #pragma unroll
        for (int o = 16; o; o >>= 1) m = fmaxf(m, __shfl_xor_sync(0xffffffffu, m, o));
        if (c == 0) atomicMax(&g_w2max_bits, fenc(m));
    }
}

// ---------------- K2: F1/F2 tables + zero D ----------------
__global__ void k_factorsA() {
    const int j = blockIdx.x * 256 + threadIdx.x;     // 0..16383
    float w2 = g_wh2[j];
    g_F1[j] = expf(w2);
    g_F2[j] = expf(ALPHA * w2);
    float4* D4 = (float4*)g_D;
    const float4 z = make_float4(0.f, 0.f, 0.f, 0.f);
    #pragma unroll
    for (int u = 0; u < 16; u++) D4[u * 16384 + j] = z;
}

// ---------------- K3: G1/G2 tables + zero S ----------------
__global__ void k_factorsB() {
    const int j = blockIdx.x * 256 + threadIdx.x;     // 0..8191
    const float w2m = fdec(g_w2max_bits);
    float w1 = g_wh1[j];
    float x  = w1 + w2m;
    float B  = x > 0.f ? x : ALPHA * x;
    g_G1[j] = expf(w1 - B);
    g_G2[j] = expf(ALPHA * w1 - B);
    g_S[j]  = 0.f;
}

// ---------------- K4: persistent fused masked-softmax attention (512 thr, 2x8 warps) -----
__global__ void __launch_bounds__(THREADS, 2)
k_attn(const float* __restrict__ adj) {
    extern __shared__ char smem[];
    const uint32_t sb = smem_u32(smem);

    const int t    = threadIdx.x;
    const int lane = t & 31, warp = t >> 5;   // 16 warps
    const int rg   = t >> 4;                  // 0..31: P rows rg and rg+32
    const int q    = t & 15;                  // col quad (4 cols)
    const int wi   = warp >> 3, wc = warp & 7;   // warp tile: rows wi*32, cols wc*16

    const int s = (int)(((long long)blockIdx.x * NJOBS) / GRID_ATTN);
    const int e = (int)(((long long)(blockIdx.x + 1) * NJOBS) / GRID_ATTN);

    // V stage loader; ALWAYS commits a group
    auto load_stage = [&](int m) {
        if (m < e) {
            const uint32_t VB = sb + SM_V + (m & 3) * 16384;
            const int jo = (m & (NTJ - 1)) * TJ;
            #pragma unroll
            for (int u = 0; u < 2; u++) {
                const int idx = t + u * THREADS;
                const int row = idx >> 4, seg = idx & 15;
                const __half* src = &g_whh[(size_t)(jo + row) * OUT_DIM + seg * 8];
                const uint32_t dst = VB + (seg >> 3) * 8192 + swz(row * 128 + (seg & 7) * 16);
                asm volatile("cp.async.cg.shared.global [%0], [%1], 16;" :: "r"(dst), "l"(src));
            }
        }
        asm volatile("cp.async.commit_group;" ::: "memory");
    };

    // adj + factor register prefetch for job m (2 rows x 4 cols)
    float4 av[2], f1q, f2q;
    auto prefetch = [&](int m) {
        if (m < e) {
            const int jo = (m & (NTJ - 1)) * TJ;
            const float* base = adj + ((size_t)(m >> 8) * TI + rg) * N_GENES + jo + q * 4;
            av[0] = __ldg((const float4*)base);
            av[1] = __ldg((const float4*)(base + (size_t)32 * N_GENES));
            f1q = *(const float4*)&g_F1[jo + q * 4];
            f2q = *(const float4*)&g_F2[jo + q * 4];
        }
    };

    float Tr[2], G1r[2], G2r[2], sacc[2];
    float d[2][2][4];
    uint32_t dh[2][2][2];

    auto load_row_consts = [&](int it) {
        #pragma unroll
        for (int r = 0; r < 2; r++) {
            const int i = it * TI + rg + r * 32;
            Tr[r]  = g_wh1[i];
            G1r[r] = g_G1[i];
            G2r[r] = g_G2[i];
            sacc[r] = 0.f;
        }
    };
    auto reset_D = [&]() {
        #pragma unroll
        for (int ah = 0; ah < 2; ah++)
            #pragma unroll
            for (int n = 0; n < 2; n++) {
                d[ah][n][0] = d[ah][n][1] = d[ah][n][2] = d[ah][n][3] = 0.f;
                dh[ah][n][0] = dh[ah][n][1] = 0u;
            }
    };
    auto fold = [&]() {
        #pragma unroll
        for (int ah = 0; ah < 2; ah++)
            #pragma unroll
            for (int n = 0; n < 2; n++) {
                float2 lo = __half22float2(*(__half2*)&dh[ah][n][0]);
                float2 hi = __half22float2(*(__half2*)&dh[ah][n][1]);
                d[ah][n][0] += lo.x; d[ah][n][1] += lo.y;
                d[ah][n][2] += hi.x; d[ah][n][3] += hi.y;
                dh[ah][n][0] = 0u;   dh[ah][n][1] = 0u;
            }
    };
    auto flush_S = [&](int it) {
        #pragma unroll
        for (int r = 0; r < 2; r++) {
            float v = sacc[r];
            v += __shfl_xor_sync(0xffffffffu, v, 8);
            v += __shfl_xor_sync(0xffffffffu, v, 4);
            v += __shfl_xor_sync(0xffffffffu, v, 2);
            v += __shfl_xor_sync(0xffffffffu, v, 1);
            if (q == 0) atomicAdd(&g_S[it * TI + rg + r * 32], v);
        }
    };
    auto flush_D = [&](int it) {
        fold();
        #pragma unroll
        for (int ah = 0; ah < 2; ah++) {
            const int r1 = wi * 32 + ah * 16 + (lane >> 2);
            #pragma unroll
            for (int n = 0; n < 2; n++) {
                const int c = wc * 16 + n * 8 + (lane & 3) * 2;
                float* p0 = &g_D[(size_t)(it * TI + r1) * OUT_DIM + c];
                float* p1 = &g_D[(size_t)(it * TI + r1 + 8) * OUT_DIM + c];
                atomicAdd(p0,     d[ah][n][0]);
                atomicAdd(p0 + 1, d[ah][n][1]);
                atomicAdd(p1,     d[ah][n][2]);
                atomicAdd(p1 + 1, d[ah][n][3]);
                d[ah][n][0] = d[ah][n][1] = d[ah][n][2] = d[ah][n][3] = 0.f;
            }
        }
    };
    // build P tile for job m into PB[m&1]; 2 rows x 4 cols per thread
    auto build_P = [&](int m) {
        const uint32_t PB = sb + SM_P + (m & 1) * 8192;
        const int jo = (m & (NTJ - 1)) * TJ;
        const float4 w2q = *(const float4*)&g_wh2[jo + q * 4];
        #pragma unroll
        for (int r = 0; r < 2; r++) {
            const float T = Tr[r], G1 = G1r[r], G2 = G2r[r];
            float x0 = T + w2q.x, x1 = T + w2q.y, x2 = T + w2q.z, x3 = T + w2q.w;
            float e0 = fmaxf(G1 * f1q.x, G2 * f2q.x);   // exp(lrelu(x)-B), monotone split
            float e1 = fmaxf(G1 * f1q.y, G2 * f2q.y);
            float e2 = fmaxf(G1 * f1q.z, G2 * f2q.z);
            float e3 = fmaxf(G1 * f1q.w, G2 * f2q.w);
            float p0 = (av[r].x != 0.f && x0 != 0.f) ? e0 : 0.f;
            float p1 = (av[r].y != 0.f && x1 != 0.f) ? e1 : 0.f;
            float p2 = (av[r].z != 0.f && x2 != 0.f) ? e2 : 0.f;
            float p3 = (av[r].w != 0.f && x3 != 0.f) ? e3 : 0.f;
            sacc[r] += (p0 + p1) + (p2 + p3);
            __half2 h01 = __floats2half2_rn(p0, p1);
            __half2 h23 = __floats2half2_rn(p2, p3);
            asm volatile("st.shared.v2.b32 [%0], {%1, %2};"
                         :: "r"(PB + swz((rg + r * 32) * 128 + q * 8)),
                            "r"(*(uint32_t*)&h01), "r"(*(uint32_t*)&h23));
        }
    };

    // ---- prologue ----
    prefetch(s);
    load_stage(s);
    load_stage(s + 1);
    load_stage(s + 2);
    int cur_it = s >> 8;
    load_row_consts(cur_it);
    reset_D();

    // ---- main loop ----
    for (int m = s; m < e; m++) {
        const uint32_t PB = sb + SM_P + (m & 1) * 8192;
        const uint32_t VB = sb + SM_V + (m & 3) * 16384;

        asm volatile("cp.async.wait_group 2;" ::: "memory");   // V[m] resident
        __syncthreads();   // also: MMA m-2 done -> PB[m&1] free

        load_stage(m + 3);

        const int it = m >> 8;
        if (it != cur_it) {            // boundary: previous tile flushed post-MMA below
            cur_it = it;
            load_row_consts(it);       // resets sacc
        }

        build_P(m);
        prefetch(m + 1);               // hidden under MMA
        __syncthreads();               // P[m] visible

        // ---- MMA: D(32x16 per warp) += P(32x64) @ V(64x16), fp16 accumulate ----
        #pragma unroll
        for (int ks = 0; ks < 4; ks++) {
            uint32_t afr[2][4];
            #pragma unroll
            for (int ah = 0; ah < 2; ah++) {
                const uint32_t aaddr = PB + swz((wi * 32 + ah * 16 + (lane & 15)) * 128
                                                + ks * 32 + (lane >> 4) * 16);
                asm volatile("ldmatrix.sync.aligned.m8n8.x4.shared.b16 {%0,%1,%2,%3},[%4];\n"
                             : "=r"(afr[ah][0]), "=r"(afr[ah][1]),
                               "=r"(afr[ah][2]), "=r"(afr[ah][3]) : "r"(aaddr));
            }
            uint32_t bfr[4];
            const int atom = wc >> 2;
            const int cin0 = (wc & 3) * 16 + (lane >> 4) * 8;
            const uint32_t baddr = VB + atom * 8192
                                 + swz((ks * 16 + (lane & 15)) * 128 + cin0 * 2);
            asm volatile("ldmatrix.sync.aligned.m8n8.x4.trans.shared.b16 {%0,%1,%2,%3},[%4];\n"
                         : "=r"(bfr[0]), "=r"(bfr[1]), "=r"(bfr[2]), "=r"(bfr[3]) : "r"(baddr));
            #pragma unroll
            for (int ah = 0; ah < 2; ah++)
                #pragma unroll
                for (int n = 0; n < 2; n++) {
                    asm volatile(
                        "mma.sync.aligned.m16n8k16.row.col.f16.f16.f16.f16 "
                        "{%0,%1},{%2,%3,%4,%5},{%6,%7},{%0,%1};\n"
                        : "+r"(dh[ah][n][0]), "+r"(dh[ah][n][1])
                        : "r"(afr[ah][0]), "r"(afr[ah][1]), "r"(afr[ah][2]), "r"(afr[ah][3]),
                          "r"(bfr[n * 2]), "r"(bfr[n * 2 + 1]));
                }
        }

        // flush at i-tile end (or range end); else fold fp16->fp32 every 2 tiles
        if (m + 1 == e || ((m + 1) >> 8) != it) {
            flush_S(it);
            flush_D(it);               // fold() inside; resets d/dh
        } else if (m & 1) {
            fold();
        }
    }
}

// ---------------- K5: normalize + ELU ----------------
__global__ void k_combine(float* __restrict__ out) {
    const int i = blockIdx.x, c = threadIdx.x;
    const float s = g_S[i];
    const size_t idx = (size_t)i * OUT_DIM + c;
    float v = g_D[idx] / s;
    out[idx] = v > 0.f ? v : expm1f(v);
}

// ---------------- launch ----------------
extern "C" void kernel_launch(void* const* d_in, const int* in_sizes, int n_in,
                              void* d_out, int out_size) {
    const float* inp = (const float*)d_in[0];   // [16384, 256]
    const float* adj = (const float*)d_in[1];   // [8192, 16384]
    const float* W   = (const float*)d_in[2];   // [256, 128]
    const float* a   = (const float*)d_in[3];   // [256, 1]
    float* out = (float*)d_out;                 // [8192, 128]

    cudaFuncSetAttribute(k_attn, cudaFuncAttributeMaxDynamicSharedMemorySize, SMEM_BYTES);

    k_gemm1   <<<N_GENES / 8, 128>>>(inp, W, a);           // launch 1
    k_factorsA<<<N_GENES / 256, 256>>>();                  // launch 2
    k_factorsB<<<N_REG / 256, 256>>>();                    // launch 3
    k_attn    <<<GRID_ATTN, THREADS, SMEM_BYTES>>>(adj);   // launch 4 (ncu target)
    k_combine <<<N_REG, OUT_DIM>>>(out);                   // launch 5
}

// round 12
// speedup vs baseline: 1.4227x; 1.4227x over previous
#include <cuda_runtime.h>
#include <cuda_fp16.h>
#include <cstdint>

#define N_GENES 16384
#define N_REG   8192
#define D_MODEL 256
#define OUT_DIM 128
#define ALPHA   0.2f

#define TI 64                    // regulon rows per i-tile
#define TJ 64                    // j per tile (MMA K)
#define NTJ 256                  // j-tiles per i-tile
#define N_ITILES (N_REG / TI)    // 128
#define NJOBS (N_ITILES * NTJ)   // 32768
#define NQUADS (NJOBS / 4)       // 8192
#define GRID_ATTN 304            // 152 SMs x 2 CTAs

// smem layout (per CTA 80 KB -> 2 CTAs/SM)
#define SM_P    0                      // 2 x 8 KB P double buffer
#define SM_V    16384                  // 4 x 16 KB V stages (fp16, 2 swizzled 64-col atoms)
#define SMEM_BYTES 81920

// ---------------- device scratch ----------------
__device__ __align__(16) __half g_whh[N_GENES * OUT_DIM];   // w_h fp16, row-major
__device__ float  g_wh1[N_REG];
__device__ float  g_wh2[N_GENES];
__device__ float  g_F1 [N_GENES];
__device__ float  g_F2 [N_GENES];
__device__ float  g_G1 [N_REG];
__device__ float  g_G2 [N_REG];
__device__ unsigned g_w2max_bits;
__device__ float  g_D  [(size_t)N_REG * OUT_DIM];           // accumulated D (atomics)
__device__ float  g_S  [N_REG];                             // accumulated S (atomics)

// ---------------- helpers ----------------
static __device__ __forceinline__ uint32_t swz(uint32_t x) { return x ^ ((x >> 3) & 0x70); }
static __device__ __forceinline__ uint32_t smem_u32(const void* p) {
    return (uint32_t)__cvta_generic_to_shared(p);
}
static __device__ __forceinline__ uint64_t pk2(float x, float y) {
    uint64_t r; asm("mov.b64 %0, {%1, %2};" : "=l"(r) : "f"(x), "f"(y)); return r;
}
static __device__ __forceinline__ void fma2(uint64_t& acc, uint64_t a, uint64_t b) {
    asm volatile("fma.rn.f32x2 %0, %1, %2, %0;" : "+l"(acc) : "l"(a), "l"(b));
}
static __device__ __forceinline__ unsigned fenc(float f) {
    unsigned u = __float_as_uint(f);
    return (u & 0x80000000u) ? ~u : (u | 0x80000000u);
}
static __device__ __forceinline__ float fdec(unsigned k) {
    unsigned u = (k & 0x80000000u) ? (k ^ 0x80000000u) : ~k;
    return __uint_as_float(u);
}

// ---------------- K1: w_h = input @ W  (+fused wh1/wh2/max) ----------------
__global__ void k_gemm1(const float* __restrict__ inp, const float* __restrict__ W,
                        const float* __restrict__ a) {
    __shared__ __align__(16) float s_t[D_MODEL][8];   // [k][r]
    __shared__ float sred[4][16];
    const int c  = threadIdx.x;          // 0..127
    const int r0 = blockIdx.x * 8;
    if (blockIdx.x == 0 && c == 0) g_w2max_bits = 0u;
    #pragma unroll
    for (int u = 0; u < 16; u++) {
        const int idx = c + u * 128;
        const int r = idx >> 8, k = idx & 255;
        s_t[k][r] = inp[(size_t)(r0 + r) * D_MODEL + k];
    }
    __syncthreads();

    uint64_t a01 = 0, a23 = 0, a45 = 0, a67 = 0;
    #pragma unroll 4
    for (int k = 0; k < D_MODEL; k++) {
        const float w = __ldg(&W[k * OUT_DIM + c]);
        const uint64_t ww = pk2(w, w);
        ulonglong2 lo = *(const ulonglong2*)&s_t[k][0];
        ulonglong2 hi = *(const ulonglong2*)&s_t[k][4];
        fma2(a01, lo.x, ww);
        fma2(a23, lo.y, ww);
        fma2(a45, hi.x, ww);
        fma2(a67, hi.y, ww);
    }
    float v[8];
    v[0] = __uint_as_float((uint32_t)a01); v[1] = __uint_as_float((uint32_t)(a01 >> 32));
    v[2] = __uint_as_float((uint32_t)a23); v[3] = __uint_as_float((uint32_t)(a23 >> 32));
    v[4] = __uint_as_float((uint32_t)a45); v[5] = __uint_as_float((uint32_t)(a45 >> 32));
    v[6] = __uint_as_float((uint32_t)a67); v[7] = __uint_as_float((uint32_t)(a67 >> 32));
    #pragma unroll
    for (int r = 0; r < 8; r++)
        g_whh[(size_t)(r0 + r) * OUT_DIM + c] = __float2half(v[r]);

    const float a1 = a[c], a2 = a[OUT_DIM + c];
    const int warp = c >> 5, lane = c & 31;
    #pragma unroll
    for (int r = 0; r < 8; r++) {
        float u1 = v[r] * a1, u2 = v[r] * a2;
        #pragma unroll
        for (int o = 16; o; o >>= 1) {
            u1 += __shfl_xor_sync(0xffffffffu, u1, o);
            u2 += __shfl_xor_sync(0xffffffffu, u2, o);
        }
        if (lane == 0) { sred[warp][r] = u1; sred[warp][8 + r] = u2; }
    }
    __syncthreads();
    if (c < 32) {
        float val = (c < 16) ? (sred[0][c] + sred[1][c] + sred[2][c] + sred[3][c]) : -1e30f;
        if (c < 8) { if (r0 + c < N_REG) g_wh1[r0 + c] = val; }
        else if (c < 16) g_wh2[r0 + c - 8] = val;
        float m = (c >= 8 && c < 16) ? val : -1e30f;
        #pragma unroll
        for (int o = 16; o; o >>= 1) m = fmaxf(m, __shfl_xor_sync(0xffffffffu, m, o));
        if (c == 0) atomicMax(&g_w2max_bits, fenc(m));
    }
}

// ---------------- K2: F1/F2 tables + zero D ----------------
__global__ void k_factorsA() {
    const int j = blockIdx.x * 256 + threadIdx.x;     // 0..16383
    float w2 = g_wh2[j];
    g_F1[j] = expf(w2);
    g_F2[j] = expf(ALPHA * w2);
    float4* D4 = (float4*)g_D;
    const float4 z = make_float4(0.f, 0.f, 0.f, 0.f);
    #pragma unroll
    for (int u = 0; u < 16; u++) D4[u * 16384 + j] = z;
}

// ---------------- K3: G1/G2 tables + zero S ----------------
__global__ void k_factorsB() {
    const int j = blockIdx.x * 256 + threadIdx.x;     // 0..8191
    const float w2m = fdec(g_w2max_bits);
    float w1 = g_wh1[j];
    float x  = w1 + w2m;
    float B  = x > 0.f ? x : ALPHA * x;
    g_G1[j] = expf(w1 - B);
    g_G2[j] = expf(ALPHA * w1 - B);
    g_S[j]  = 0.f;
}

// ---------------- K4: persistent fused masked-softmax attention (quad-unrolled skew) -----
__global__ void __launch_bounds__(256, 2)
k_attn(const float* __restrict__ adj) {
    extern __shared__ char smem[];
    const uint32_t sb = smem_u32(smem);

    const int t    = threadIdx.x;
    const int lane = t & 31, warp = t >> 5;   // 8 warps
    const int rh   = lane >> 4;               // row half within warp's 8 rows
    const int q    = lane & 15;               // col quad (4 cols)
    const int wi   = warp >> 2, wc = warp & 3;

    // even static partition of the job space, in quads (s,e multiples of 4;
    // i-tile boundaries are multiples of 256, hence quad-aligned)
    const int s = 4 * (int)(((long long)blockIdx.x * NQUADS) / GRID_ATTN);
    const int e = 4 * (int)(((long long)(blockIdx.x + 1) * NQUADS) / GRID_ATTN);

    // V stage loader into explicit slot; ALWAYS commits a group
    auto load_stage = [&](int m, int slot) {
        if (m < e) {
            const uint32_t VB = sb + SM_V + slot * 16384;
            const int jo = (m & (NTJ - 1)) * TJ;
            #pragma unroll
            for (int u = 0; u < 4; u++) {
                const int idx = t + u * 256;
                const int row = idx >> 4, seg = idx & 15;
                const __half* src = &g_whh[(size_t)(jo + row) * OUT_DIM + seg * 8];
                const uint32_t dst = VB + (seg >> 3) * 8192 + swz(row * 128 + (seg & 7) * 16);
                asm volatile("cp.async.cg.shared.global [%0], [%1], 16;" :: "r"(dst), "l"(src));
            }
        }
        asm volatile("cp.async.commit_group;" ::: "memory");
    };

    // adj + factor register prefetch for job m
    float4 av[4], f1q, f2q;
    auto prefetch = [&](int m) {
        if (m < e) {
            const int jo = (m & (NTJ - 1)) * TJ;
            const float* base = adj + ((size_t)(m >> 8) * TI + warp * 8 + rh * 4) * N_GENES
                              + jo + q * 4;
            #pragma unroll
            for (int r = 0; r < 4; r++)
                av[r] = __ldg((const float4*)(base + (size_t)r * N_GENES));
            f1q = *(const float4*)&g_F1[jo + q * 4];
            f2q = *(const float4*)&g_F2[jo + q * 4];
        }
    };

    float G1r[4], G2r[4], sacc[4];
    float d[2][4][4];
    uint32_t dh[2][4][2];

    auto load_row_consts = [&](int it) {
        #pragma unroll
        for (int r = 0; r < 4; r++) {
            const int i = it * TI + warp * 8 + rh * 4 + r;
            G1r[r] = g_G1[i];
            G2r[r] = g_G2[i];
            sacc[r] = 0.f;
        }
    };
    auto reset_D = [&]() {
        #pragma unroll
        for (int ah = 0; ah < 2; ah++)
            #pragma unroll
            for (int n = 0; n < 4; n++) {
                d[ah][n][0] = d[ah][n][1] = d[ah][n][2] = d[ah][n][3] = 0.f;
                dh[ah][n][0] = dh[ah][n][1] = 0u;
            }
    };
    auto fold = [&]() {
        #pragma unroll
        for (int ah = 0; ah < 2; ah++)
            #pragma unroll
            for (int n = 0; n < 4; n++) {
                float2 lo = __half22float2(*(__half2*)&dh[ah][n][0]);
                float2 hi = __half22float2(*(__half2*)&dh[ah][n][1]);
                d[ah][n][0] += lo.x; d[ah][n][1] += lo.y;
                d[ah][n][2] += hi.x; d[ah][n][3] += hi.y;
                dh[ah][n][0] = 0u;   dh[ah][n][1] = 0u;
            }
    };
    auto flush_S = [&](int it) {
        #pragma unroll
        for (int r = 0; r < 4; r++) {
            float v = sacc[r];
            v += __shfl_xor_sync(0xffffffffu, v, 8);
            v += __shfl_xor_sync(0xffffffffu, v, 4);
            v += __shfl_xor_sync(0xffffffffu, v, 2);
            v += __shfl_xor_sync(0xffffffffu, v, 1);
            if (q == 0) atomicAdd(&g_S[it * TI + warp * 8 + rh * 4 + r], v);
        }
    };
    auto flush_D = [&](int it) {
        fold();
        #pragma unroll
        for (int ah = 0; ah < 2; ah++) {
            const int r1 = wi * 32 + ah * 16 + (lane >> 2);
            #pragma unroll
            for (int n = 0; n < 4; n++) {
                const int c = wc * 32 + n * 8 + (lane & 3) * 2;
                float* p0 = &g_D[(size_t)(it * TI + r1) * OUT_DIM + c];
                float* p1 = &g_D[(size_t)(it * TI + r1 + 8) * OUT_DIM + c];
                atomicAdd(p0,     d[ah][n][0]);
                atomicAdd(p0 + 1, d[ah][n][1]);
                atomicAdd(p1,     d[ah][n][2]);
                atomicAdd(p1 + 1, d[ah][n][3]);
                d[ah][n][0] = d[ah][n][1] = d[ah][n][2] = d[ah][n][3] = 0.f;
            }
        }
    };
    // build P tile for job m into buffer PB (adj in {0,1}: p = adj * e, exact)
    auto build_P = [&](int m, uint32_t PB) {
        #pragma unroll
        for (int r = 0; r < 4; r++) {
            const float G1 = G1r[r], G2 = G2r[r];
            float p0 = av[r].x * fmaxf(G1 * f1q.x, G2 * f2q.x);
            float p1 = av[r].y * fmaxf(G1 * f1q.y, G2 * f2q.y);
            float p2 = av[r].z * fmaxf(G1 * f1q.z, G2 * f2q.z);
            float p3 = av[r].w * fmaxf(G1 * f1q.w, G2 * f2q.w);
            sacc[r] += (p0 + p1) + (p2 + p3);
            __half2 h01 = __floats2half2_rn(p0, p1);
            __half2 h23 = __floats2half2_rn(p2, p3);
            asm volatile("st.shared.v2.b32 [%0], {%1, %2};"
                         :: "r"(PB + swz((warp * 8 + rh * 4 + r) * 128 + q * 8)),
                            "r"(*(uint32_t*)&h01), "r"(*(uint32_t*)&h23));
        }
    };

    // ---- prologue ----
    prefetch(s);
    load_stage(s, 0);
    load_stage(s + 1, 1);
    load_stage(s + 2, 2);
    int it_b = s >> 8;
    load_row_consts(it_b);
    reset_D();
    build_P(s, sb + SM_P);
    prefetch(s + 1);

    // ---- main loop: quad-unrolled, one barrier per tile ----
    for (int mb = s; mb < e; mb += 4) {
        #pragma unroll
        for (int u = 0; u < 4; u++) {
            const int m = mb + u;
            const uint32_t PB = sb + SM_P + (u & 1) * 8192;          // compile-time
            const uint32_t VB = sb + SM_V + u * 16384;               // compile-time

            asm volatile("cp.async.wait_group 2;" ::: "memory");     // V[m] resident
            __syncthreads();   // P[m] visible; MMA m-1 done -> PB[(m+1)&1] + slot free

            load_stage(m + 3, (u + 3) & 3);

            if (m + 1 < e) {
                if (u == 3) {                       // only slot where (m+1)%256 can be 0
                    const int it_n = (m + 1) >> 8;
                    if (it_n != it_b) {
                        flush_S(it_b);
                        it_b = it_n;
                        load_row_consts(it_b);      // resets sacc
                    }
                }
                build_P(m + 1, sb + SM_P + ((u + 1) & 1) * 8192);
                prefetch(m + 2);
            }

            // ---- MMA: D(32x32 per warp) += P(32x64) @ V(64x32), fp16 accumulate ----
            #pragma unroll
            for (int ks = 0; ks < 4; ks++) {
                uint32_t afr[2][4];
                #pragma unroll
                for (int ah = 0; ah < 2; ah++) {
                    const uint32_t aaddr = PB + swz((wi * 32 + ah * 16 + (lane & 15)) * 128
                                                    + ks * 32 + (lane >> 4) * 16);
                    asm volatile("ldmatrix.sync.aligned.m8n8.x4.shared.b16 {%0,%1,%2,%3},[%4];\n"
                                 : "=r"(afr[ah][0]), "=r"(afr[ah][1]),
                                   "=r"(afr[ah][2]), "=r"(afr[ah][3]) : "r"(aaddr));
                }
                uint32_t bfr[8];
                const int atom = wc >> 1;
                const int cin0 = (wc & 1) * 32 + (lane >> 4) * 8;
                const uint32_t brow = (ks * 16 + (lane & 15)) * 128;
                const uint32_t baddr0 = VB + atom * 8192 + swz(brow + cin0 * 2);
                asm volatile("ldmatrix.sync.aligned.m8n8.x4.trans.shared.b16 {%0,%1,%2,%3},[%4];\n"
                             : "=r"(bfr[0]), "=r"(bfr[1]), "=r"(bfr[2]), "=r"(bfr[3]) : "r"(baddr0));
                const uint32_t baddr1 = VB + atom * 8192 + swz(brow + (cin0 + 16) * 2);
                asm volatile("ldmatrix.sync.aligned.m8n8.x4.trans.shared.b16 {%0,%1,%2,%3},[%4];\n"
                             : "=r"(bfr[4]), "=r"(bfr[5]), "=r"(bfr[6]), "=r"(bfr[7]) : "r"(baddr1));
                #pragma unroll
                for (int ah = 0; ah < 2; ah++)
                    #pragma unroll
                    for (int n = 0; n < 4; n++) {
                        asm volatile(
                            "mma.sync.aligned.m16n8k16.row.col.f16.f16.f16.f16 "
                            "{%0,%1},{%2,%3,%4,%5},{%6,%7},{%0,%1};\n"
                            : "+r"(dh[ah][n][0]), "+r"(dh[ah][n][1])
                            : "r"(afr[ah][0]), "r"(afr[ah][1]), "r"(afr[ah][2]), "r"(afr[ah][3]),
                              "r"(bfr[n * 2]), "r"(bfr[n * 2 + 1]));
                    }
            }

            if (u == 3) {   // quad end: flush at i-tile/range end, else fold (4-tile cadence)
                if (m + 1 == e || ((m + 1) & (NTJ * TJ / TJ - 1)) == 0) {
                    // (m+1) % 256 == 0  <=>  i-tile end
                    flush_D(m >> 8);
                } else {
                    fold();
                }
            }
        }
    }
    flush_S(it_b);   // last i-tile's S
}

// ---------------- K5: normalize + ELU ----------------
__global__ void k_combine(float* __restrict__ out) {
    const int i = blockIdx.x, c = threadIdx.x;
    const float s = g_S[i];
    const size_t idx = (size_t)i * OUT_DIM + c;
    float v = g_D[idx] / s;
    out[idx] = v > 0.f ? v : expm1f(v);
}

// ---------------- launch ----------------
extern "C" void kernel_launch(void* const* d_in, const int* in_sizes, int n_in,
                              void* d_out, int out_size) {
    const float* inp = (const float*)d_in[0];   // [16384, 256]
    const float* adj = (const float*)d_in[1];   // [8192, 16384]
    const float* W   = (const float*)d_in[2];   // [256, 128]
    const float* a   = (const float*)d_in[3];   // [256, 1]
    float* out = (float*)d_out;                 // [8192, 128]

    cudaFuncSetAttribute(k_attn, cudaFuncAttributeMaxDynamicSharedMemorySize, SMEM_BYTES);

    k_gemm1   <<<N_GENES / 8, 128>>>(inp, W, a);       // launch 1
    k_factorsA<<<N_GENES / 256, 256>>>();              // launch 2
    k_factorsB<<<N_REG / 256, 256>>>();                // launch 3
    k_attn    <<<GRID_ATTN, 256, SMEM_BYTES>>>(adj);   // launch 4 (ncu target)
    k_combine <<<N_REG, OUT_DIM>>>(out);               // launch 5
}

// round 13
// speedup vs baseline: 1.8431x; 1.2955x over previous
#include <cuda_runtime.h>
#include <cuda_fp16.h>
#include <cstdint>

#define N_GENES 16384
#define N_REG   8192
#define D_MODEL 256
#define OUT_DIM 128
#define ALPHA   0.2f

#define TI 64
#define TJ 64
#define NTJ 256
#define N_ITILES (N_REG / TI)
#define NJOBS (N_ITILES * NTJ)
#define NQUADS (NJOBS / 4)
#define GRID_ATTN 304

#define SM_P    0
#define SM_V    16384
#define SMEM_BYTES 81920
#define SMEM_G1 65536          // gemm1h: 2 stages x (16KB A + 16KB B)

// ---------------- device scratch ----------------
__device__ __align__(16) __half g_inph[N_GENES * D_MODEL];  // inp fp16
__device__ __align__(16) __half g_Wh  [D_MODEL * OUT_DIM];  // W fp16
__device__ __align__(16) __half g_whh [N_GENES * OUT_DIM];  // w_h fp16
__device__ float  g_wh1[N_REG];
__device__ float  g_wh2[N_GENES];
__device__ float  g_F1 [N_GENES];
__device__ float  g_F2 [N_GENES];
__device__ float  g_G1 [N_REG];
__device__ float  g_G2 [N_REG];
__device__ unsigned g_w2max_bits;
__device__ float  g_D  [(size_t)N_REG * OUT_DIM];
__device__ float  g_S  [N_REG];

// ---------------- helpers ----------------
static __device__ __forceinline__ uint32_t swz(uint32_t x) { return x ^ ((x >> 3) & 0x70); }
static __device__ __forceinline__ uint32_t smem_u32(const void* p) {
    return (uint32_t)__cvta_generic_to_shared(p);
}
static __device__ __forceinline__ unsigned fenc(float f) {
    unsigned u = __float_as_uint(f);
    return (u & 0x80000000u) ? ~u : (u | 0x80000000u);
}
static __device__ __forceinline__ float fdec(unsigned k) {
    unsigned u = (k & 0x80000000u) ? (k ^ 0x80000000u) : ~k;
    return __uint_as_float(u);
}

// ---------------- K1: prep — fp16 conversions + zero D/S ----------------
__global__ void k_prep(const float* __restrict__ inp, const float* __restrict__ W) {
    const int t = blockIdx.x * 256 + threadIdx.x;    // 0 .. 1048575
    if (t == 0) g_w2max_bits = 0u;
    {   // inp -> fp16 (4 elems/thread)
        float4 v = *(const float4*)&inp[(size_t)t * 4];
        __half2 h0 = __floats2half2_rn(v.x, v.y);
        __half2 h1 = __floats2half2_rn(v.z, v.w);
        uint2 u; u.x = *(uint32_t*)&h0; u.y = *(uint32_t*)&h1;
        *(uint2*)&g_inph[(size_t)t * 4] = u;
    }
    if (t < (D_MODEL * OUT_DIM) / 4) {   // W -> fp16
        float4 v = *(const float4*)&W[t * 4];
        __half2 h0 = __floats2half2_rn(v.x, v.y);
        __half2 h1 = __floats2half2_rn(v.z, v.w);
        uint2 u; u.x = *(uint32_t*)&h0; u.y = *(uint32_t*)&h1;
        *(uint2*)&g_Wh[t * 4] = u;
    }
    if (t < ((size_t)N_REG * OUT_DIM) / 4)   // zero D
        ((float4*)g_D)[t] = make_float4(0.f, 0.f, 0.f, 0.f);
    if (t < N_REG) g_S[t] = 0.f;
}

// ---------------- K2: w_h = inp @ W via HMMA (+fused wh1/wh2/max) ----------------
__global__ void __launch_bounds__(256, 1)
k_gemm1h(const float* __restrict__ a) {
    extern __shared__ char smem[];
    const uint32_t sb = smem_u32(smem);
    float* sP1 = (float*)(smem);            // reuse stage-0 region post-mainloop
    float* sP2 = (float*)(smem + 1024);

    const int t    = threadIdx.x;
    const int lane = t & 31, warp = t >> 5;       // 8 warps
    const int wi   = warp >> 1, wc = warp & 1;    // warp tile: rows wi*32, cols wc*64
    const int r0   = blockIdx.x * 128;

    // stage layout: A[st] at st*32768, B[st] at st*32768 + 16384
    auto load_chunk = [&](int kc, int st) {
        const uint32_t AB = sb + st * 32768;
        const uint32_t BB = AB + 16384;
        #pragma unroll
        for (int u = 0; u < 4; u++) {
            const int idx = t + u * 256;
            {   // A: 128 rows x 64 halves (128B rows)
                const int row = idx >> 3, ch = idx & 7;
                const __half* src = &g_inph[(size_t)(r0 + row) * D_MODEL + kc * 64 + ch * 8];
                asm volatile("cp.async.cg.shared.global [%0], [%1], 16;"
                             :: "r"(AB + swz(row * 128 + ch * 16)), "l"(src));
            }
            {   // B: 64 k-rows x 128 halves (2 atoms of 64 cols)
                const int row = idx >> 4, seg = idx & 15;
                const __half* src = &g_Wh[(kc * 64 + row) * OUT_DIM + seg * 8];
                const uint32_t dst = BB + (seg >> 3) * 8192 + swz(row * 128 + (seg & 7) * 16);
                asm volatile("cp.async.cg.shared.global [%0], [%1], 16;" :: "r"(dst), "l"(src));
            }
        }
        asm volatile("cp.async.commit_group;" ::: "memory");
    };

    float d[2][8][4];
    #pragma unroll
    for (int ah = 0; ah < 2; ah++)
        #pragma unroll
        for (int n = 0; n < 8; n++)
            #pragma unroll
            for (int k = 0; k < 4; k++) d[ah][n][k] = 0.f;

    load_chunk(0, 0);
    #pragma unroll
    for (int kc = 0; kc < 4; kc++) {
        if (kc + 1 < 4) load_chunk(kc + 1, (kc + 1) & 1);
        if (kc + 1 < 4) asm volatile("cp.async.wait_group 1;" ::: "memory");
        else            asm volatile("cp.async.wait_group 0;" ::: "memory");
        __syncthreads();

        const uint32_t AB = sb + (kc & 1) * 32768;
        const uint32_t BB = AB + 16384;
        #pragma unroll
        for (int ks = 0; ks < 4; ks++) {
            uint32_t afr[2][4];
            #pragma unroll
            for (int ah = 0; ah < 2; ah++) {
                const uint32_t aaddr = AB + swz((wi * 32 + ah * 16 + (lane & 15)) * 128
                                                + ks * 32 + (lane >> 4) * 16);
                asm volatile("ldmatrix.sync.aligned.m8n8.x4.shared.b16 {%0,%1,%2,%3},[%4];\n"
                             : "=r"(afr[ah][0]), "=r"(afr[ah][1]),
                               "=r"(afr[ah][2]), "=r"(afr[ah][3]) : "r"(aaddr));
            }
            uint32_t bfr[4][4];
            #pragma unroll
            for (int nb = 0; nb < 4; nb++) {
                const int cin = nb * 16 + (lane >> 4) * 8;   // within warp's 64-col atom (atom = wc)
                const uint32_t baddr = BB + wc * 8192
                                     + swz((ks * 16 + (lane & 15)) * 128 + cin * 2);
                asm volatile("ldmatrix.sync.aligned.m8n8.x4.trans.shared.b16 {%0,%1,%2,%3},[%4];\n"
                             : "=r"(bfr[nb][0]), "=r"(bfr[nb][1]),
                               "=r"(bfr[nb][2]), "=r"(bfr[nb][3]) : "r"(baddr));
            }
            #pragma unroll
            for (int ah = 0; ah < 2; ah++)
                #pragma unroll
                for (int n = 0; n < 8; n++) {
                    asm volatile(
                        "mma.sync.aligned.m16n8k16.row.col.f32.f16.f16.f32 "
                        "{%0,%1,%2,%3},{%4,%5,%6,%7},{%8,%9},{%0,%1,%2,%3};\n"
                        : "+f"(d[ah][n][0]), "+f"(d[ah][n][1]),
                          "+f"(d[ah][n][2]), "+f"(d[ah][n][3])
                        : "r"(afr[ah][0]), "r"(afr[ah][1]), "r"(afr[ah][2]), "r"(afr[ah][3]),
                          "r"(bfr[n >> 1][(n & 1) * 2]), "r"(bfr[n >> 1][(n & 1) * 2 + 1]));
                }
        }
        __syncthreads();   // mma reads done before this stage is reloaded (kc+2)
    }

    // ---- epilogue: store w_h fp16 + fused wh1/wh2 partials ----
    float s1[2][2] = {{0.f,0.f},{0.f,0.f}}, s2[2][2] = {{0.f,0.f},{0.f,0.f}};
    #pragma unroll
    for (int ah = 0; ah < 2; ah++) {
        const int r1 = wi * 32 + ah * 16 + (lane >> 2);
        #pragma unroll
        for (int n = 0; n < 8; n++) {
            const int c = wc * 64 + n * 8 + (lane & 3) * 2;
            __half2 h0 = __floats2half2_rn(d[ah][n][0], d[ah][n][1]);
            __half2 h1 = __floats2half2_rn(d[ah][n][2], d[ah][n][3]);
            *(uint32_t*)&g_whh[(size_t)(r0 + r1) * OUT_DIM + c]     = *(uint32_t*)&h0;
            *(uint32_t*)&g_whh[(size_t)(r0 + r1 + 8) * OUT_DIM + c] = *(uint32_t*)&h1;
            const float a10 = a[c], a11 = a[c + 1];
            const float a20 = a[OUT_DIM + c], a21 = a[OUT_DIM + c + 1];
            s1[ah][0] += d[ah][n][0] * a10 + d[ah][n][1] * a11;
            s2[ah][0] += d[ah][n][0] * a20 + d[ah][n][1] * a21;
            s1[ah][1] += d[ah][n][2] * a10 + d[ah][n][3] * a11;
            s2[ah][1] += d[ah][n][2] * a20 + d[ah][n][3] * a21;
        }
    }
    __syncthreads();   // smem stages free for reuse as reduction buffers
    #pragma unroll
    for (int ah = 0; ah < 2; ah++)
        #pragma unroll
        for (int h = 0; h < 2; h++) {
            float v1 = s1[ah][h], v2 = s2[ah][h];
            v1 += __shfl_xor_sync(0xffffffffu, v1, 1);
            v1 += __shfl_xor_sync(0xffffffffu, v1, 2);
            v2 += __shfl_xor_sync(0xffffffffu, v2, 1);
            v2 += __shfl_xor_sync(0xffffffffu, v2, 2);
            if ((lane & 3) == 0) {
                const int row = wi * 32 + ah * 16 + h * 8 + (lane >> 2);
                sP1[wc * 128 + row] = v1;
                sP2[wc * 128 + row] = v2;
            }
        }
    __syncthreads();
    __shared__ float smax[4];
    if (t < 128) {
        const float v1 = sP1[t] + sP1[128 + t];
        const float v2 = sP2[t] + sP2[128 + t];
        if (r0 + t < N_REG) g_wh1[r0 + t] = v1;
        g_wh2[r0 + t] = v2;
        float m = v2;
        #pragma unroll
        for (int o = 16; o; o >>= 1) m = fmaxf(m, __shfl_xor_sync(0xffffffffu, m, o));
        if ((t & 31) == 0) smax[t >> 5] = m;
    }
    __syncthreads();
    if (t == 0) {
        float m = fmaxf(fmaxf(smax[0], smax[1]), fmaxf(smax[2], smax[3]));
        atomicMax(&g_w2max_bits, fenc(m));
    }
}

// ---------------- K3: exp factor tables ----------------
__global__ void k_factors() {
    const int j = blockIdx.x * 256 + threadIdx.x;     // 0..16383
    const float w2m = fdec(g_w2max_bits);
    float w2 = g_wh2[j];
    g_F1[j] = expf(w2);
    g_F2[j] = expf(ALPHA * w2);
    if (j < N_REG) {
        float w1 = g_wh1[j];
        float x  = w1 + w2m;
        float B  = x > 0.f ? x : ALPHA * x;
        g_G1[j] = expf(w1 - B);
        g_G2[j] = expf(ALPHA * w1 - B);
    }
}

// ---------------- K4: persistent fused masked-softmax attention (unchanged from R12) ----
__global__ void __launch_bounds__(256, 2)
k_attn(const float* __restrict__ adj) {
    extern __shared__ char smem[];
    const uint32_t sb = smem_u32(smem);

    const int t    = threadIdx.x;
    const int lane = t & 31, warp = t >> 5;
    const int rh   = lane >> 4;
    const int q    = lane & 15;
    const int wi   = warp >> 2, wc = warp & 3;

    const int s = 4 * (int)(((long long)blockIdx.x * NQUADS) / GRID_ATTN);
    const int e = 4 * (int)(((long long)(blockIdx.x + 1) * NQUADS) / GRID_ATTN);

    auto load_stage = [&](int m, int slot) {
        if (m < e) {
            const uint32_t VB = sb + SM_V + slot * 16384;
            const int jo = (m & (NTJ - 1)) * TJ;
            #pragma unroll
            for (int u = 0; u < 4; u++) {
                const int idx = t + u * 256;
                const int row = idx >> 4, seg = idx & 15;
                const __half* src = &g_whh[(size_t)(jo + row) * OUT_DIM + seg * 8];
                const uint32_t dst = VB + (seg >> 3) * 8192 + swz(row * 128 + (seg & 7) * 16);
                asm volatile("cp.async.cg.shared.global [%0], [%1], 16;" :: "r"(dst), "l"(src));
            }
        }
        asm volatile("cp.async.commit_group;" ::: "memory");
    };

    float4 av[4], f1q, f2q;
    auto prefetch = [&](int m) {
        if (m < e) {
            const int jo = (m & (NTJ - 1)) * TJ;
            const float* base = adj + ((size_t)(m >> 8) * TI + warp * 8 + rh * 4) * N_GENES
                              + jo + q * 4;
            #pragma unroll
            for (int r = 0; r < 4; r++)
                av[r] = __ldg((const float4*)(base + (size_t)r * N_GENES));
            f1q = *(const float4*)&g_F1[jo + q * 4];
            f2q = *(const float4*)&g_F2[jo + q * 4];
        }
    };

    float G1r[4], G2r[4], sacc[4];
    float d[2][4][4];
    uint32_t dh[2][4][2];

    auto load_row_consts = [&](int it) {
        #pragma unroll
        for (int r = 0; r < 4; r++) {
            const int i = it * TI + warp * 8 + rh * 4 + r;
            G1r[r] = g_G1[i];
            G2r[r] = g_G2[i];
            sacc[r] = 0.f;
        }
    };
    auto reset_D = [&]() {
        #pragma unroll
        for (int ah = 0; ah < 2; ah++)
            #pragma unroll
            for (int n = 0; n < 4; n++) {
                d[ah][n][0] = d[ah][n][1] = d[ah][n][2] = d[ah][n][3] = 0.f;
                dh[ah][n][0] = dh[ah][n][1] = 0u;
            }
    };
    auto fold = [&]() {
        #pragma unroll
        for (int ah = 0; ah < 2; ah++)
            #pragma unroll
            for (int n = 0; n < 4; n++) {
                float2 lo = __half22float2(*(__half2*)&dh[ah][n][0]);
                float2 hi = __half22float2(*(__half2*)&dh[ah][n][1]);
                d[ah][n][0] += lo.x; d[ah][n][1] += lo.y;
                d[ah][n][2] += hi.x; d[ah][n][3] += hi.y;
                dh[ah][n][0] = 0u;   dh[ah][n][1] = 0u;
            }
    };
    auto flush_S = [&](int it) {
        #pragma unroll
        for (int r = 0; r < 4; r++) {
            float v = sacc[r];
            v += __shfl_xor_sync(0xffffffffu, v, 8);
            v += __shfl_xor_sync(0xffffffffu, v, 4);
            v += __shfl_xor_sync(0xffffffffu, v, 2);
            v += __shfl_xor_sync(0xffffffffu, v, 1);
            if (q == 0) atomicAdd(&g_S[it * TI + warp * 8 + rh * 4 + r], v);
        }
    };
    auto flush_D = [&](int it) {
        fold();
        #pragma unroll
        for (int ah = 0; ah < 2; ah++) {
            const int r1 = wi * 32 + ah * 16 + (lane >> 2);
            #pragma unroll
            for (int n = 0; n < 4; n++) {
                const int c = wc * 32 + n * 8 + (lane & 3) * 2;
                float* p0 = &g_D[(size_t)(it * TI + r1) * OUT_DIM + c];
                float* p1 = &g_D[(size_t)(it * TI + r1 + 8) * OUT_DIM + c];
                atomicAdd(p0,     d[ah][n][0]);
                atomicAdd(p0 + 1, d[ah][n][1]);
                atomicAdd(p1,     d[ah][n][2]);
                atomicAdd(p1 + 1, d[ah][n][3]);
                d[ah][n][0] = d[ah][n][1] = d[ah][n][2] = d[ah][n][3] = 0.f;
            }
        }
    };
    auto build_P = [&](int m, uint32_t PB) {
        #pragma unroll
        for (int r = 0; r < 4; r++) {
            const float G1 = G1r[r], G2 = G2r[r];
            float p0 = av[r].x * fmaxf(G1 * f1q.x, G2 * f2q.x);
            float p1 = av[r].y * fmaxf(G1 * f1q.y, G2 * f2q.y);
            float p2 = av[r].z * fmaxf(G1 * f1q.z, G2 * f2q.z);
            float p3 = av[r].w * fmaxf(G1 * f1q.w, G2 * f2q.w);
            sacc[r] += (p0 + p1) + (p2 + p3);
            __half2 h01 = __floats2half2_rn(p0, p1);
            __half2 h23 = __floats2half2_rn(p2, p3);
            asm volatile("st.shared.v2.b32 [%0], {%1, %2};"
                         :: "r"(PB + swz((warp * 8 + rh * 4 + r) * 128 + q * 8)),
                            "r"(*(uint32_t*)&h01), "r"(*(uint32_t*)&h23));
        }
    };

    prefetch(s);
    load_stage(s, 0);
    load_stage(s + 1, 1);
    load_stage(s + 2, 2);
    int it_b = s >> 8;
    load_row_consts(it_b);
    reset_D();
    build_P(s, sb + SM_P);
    prefetch(s + 1);

    for (int mb = s; mb < e; mb += 4) {
        #pragma unroll
        for (int u = 0; u < 4; u++) {
            const int m = mb + u;
            const uint32_t PB = sb + SM_P + (u & 1) * 8192;
            const uint32_t VB = sb + SM_V + u * 16384;

            asm volatile("cp.async.wait_group 2;" ::: "memory");
            __syncthreads();

            load_stage(m + 3, (u + 3) & 3);

            if (m + 1 < e) {
                if (u == 3) {
                    const int it_n = (m + 1) >> 8;
                    if (it_n != it_b) {
                        flush_S(it_b);
                        it_b = it_n;
                        load_row_consts(it_b);
                    }
                }
                build_P(m + 1, sb + SM_P + ((u + 1) & 1) * 8192);
                prefetch(m + 2);
            }

            #pragma unroll
            for (int ks = 0; ks < 4; ks++) {
                uint32_t afr[2][4];
                #pragma unroll
                for (int ah = 0; ah < 2; ah++) {
                    const uint32_t aaddr = PB + swz((wi * 32 + ah * 16 + (lane & 15)) * 128
                                                    + ks * 32 + (lane >> 4) * 16);
                    asm volatile("ldmatrix.sync.aligned.m8n8.x4.shared.b16 {%0,%1,%2,%3},[%4];\n"
                                 : "=r"(afr[ah][0]), "=r"(afr[ah][1]),
                                   "=r"(afr[ah][2]), "=r"(afr[ah][3]) : "r"(aaddr));
                }
                uint32_t bfr[8];
                const int atom = wc >> 1;
                const int cin0 = (wc & 1) * 32 + (lane >> 4) * 8;
                const uint32_t brow = (ks * 16 + (lane & 15)) * 128;
                const uint32_t baddr0 = VB + atom * 8192 + swz(brow + cin0 * 2);
                asm volatile("ldmatrix.sync.aligned.m8n8.x4.trans.shared.b16 {%0,%1,%2,%3},[%4];\n"
                             : "=r"(bfr[0]), "=r"(bfr[1]), "=r"(bfr[2]), "=r"(bfr[3]) : "r"(baddr0));
                const uint32_t baddr1 = VB + atom * 8192 + swz(brow + (cin0 + 16) * 2);
                asm volatile("ldmatrix.sync.aligned.m8n8.x4.trans.shared.b16 {%0,%1,%2,%3},[%4];\n"
                             : "=r"(bfr[4]), "=r"(bfr[5]), "=r"(bfr[6]), "=r"(bfr[7]) : "r"(baddr1));
                #pragma unroll
                for (int ah = 0; ah < 2; ah++)
                    #pragma unroll
                    for (int n = 0; n < 4; n++) {
                        asm volatile(
                            "mma.sync.aligned.m16n8k16.row.col.f16.f16.f16.f16 "
                            "{%0,%1},{%2,%3,%4,%5},{%6,%7},{%0,%1};\n"
                            : "+r"(dh[ah][n][0]), "+r"(dh[ah][n][1])
                            : "r"(afr[ah][0]), "r"(afr[ah][1]), "r"(afr[ah][2]), "r"(afr[ah][3]),
                              "r"(bfr[n * 2]), "r"(bfr[n * 2 + 1]));
                    }
            }

            if (u == 3) {
                if (m + 1 == e || ((m + 1) & (NTJ - 1)) == 0) {
                    flush_D(m >> 8);
                } else {
                    fold();
                }
            }
        }
    }
    flush_S(it_b);
}

// ---------------- K5: normalize + ELU ----------------
__global__ void k_combine(float* __restrict__ out) {
    const int i = blockIdx.x, c = threadIdx.x;
    const float s = g_S[i];
    const size_t idx = (size_t)i * OUT_DIM + c;
    float v = g_D[idx] / s;
    out[idx] = v > 0.f ? v : expm1f(v);
}

// ---------------- launch ----------------
extern "C" void kernel_launch(void* const* d_in, const int* in_sizes, int n_in,
                              void* d_out, int out_size) {
    const float* inp = (const float*)d_in[0];   // [16384, 256]
    const float* adj = (const float*)d_in[1];   // [8192, 16384]
    const float* W   = (const float*)d_in[2];   // [256, 128]
    const float* a   = (const float*)d_in[3];   // [256, 1]
    float* out = (float*)d_out;                 // [8192, 128]

    cudaFuncSetAttribute(k_attn,  cudaFuncAttributeMaxDynamicSharedMemorySize, SMEM_BYTES);
    cudaFuncSetAttribute(k_gemm1h, cudaFuncAttributeMaxDynamicSharedMemorySize, SMEM_G1);

    k_prep   <<<(N_GENES * D_MODEL / 4) / 256, 256>>>(inp, W);   // launch 1
    k_gemm1h <<<N_GENES / 128, 256, SMEM_G1>>>(a);               // launch 2
    k_factors<<<N_GENES / 256, 256>>>();                         // launch 3
    k_attn   <<<GRID_ATTN, 256, SMEM_BYTES>>>(adj);              // launch 4 (ncu target)
    k_combine<<<N_REG, OUT_DIM>>>(out);                          // launch 5
}